// round 1
// baseline (speedup 1.0000x reference)
#include <cuda_runtime.h>

#define HID   100
#define G4    400
#define SEQ   8192
#define NCLS  20
#define TB    16

// scratch for x_proj (no cudaMalloc allowed)
__device__ float g_xp[SEQ * G4];

__device__ __forceinline__ unsigned long long ffma2(unsigned long long a,
                                                    unsigned long long b,
                                                    unsigned long long c) {
    unsigned long long d;
    asm("fma.rn.f32x2 %0, %1, %2, %3;" : "=l"(d) : "l"(a), "l"(b), "l"(c));
    return d;
}
__device__ __forceinline__ void unpack2(unsigned long long v, float& lo, float& hi) {
    asm("mov.b64 {%0, %1}, %2;" : "=f"(lo), "=f"(hi) : "l"(v));
}
__device__ __forceinline__ float sig_f(float x) {
    return __fdividef(1.f, 1.f + __expf(-x));
}
__device__ __forceinline__ float tanh_f(float x) {
    return __fdividef(2.f, 1.f + __expf(-2.f * x)) - 1.f;
}

// ---------------------------------------------------------------------------
// Kernel 1: embedding gather + x_proj GEMM (+ both biases folded in)
// grid = SEQ/TB blocks, 400 threads; thread r owns output row r for TB steps.
// ---------------------------------------------------------------------------
__global__ void __launch_bounds__(G4, 1)
proj_kernel(const int* __restrict__ seq, const float* __restrict__ emb,
            const float* __restrict__ W_ih, const float* __restrict__ b_ih,
            const float* __restrict__ b_hh) {
    __shared__ float es[TB * HID];
    __shared__ int   sid[TB];
    const int tid = threadIdx.x;
    const int t0  = blockIdx.x * TB;

    if (tid < TB) sid[tid] = seq[t0 + tid];
    __syncthreads();
    for (int n = tid; n < TB * HID; n += G4) {
        int tt = n / HID, k = n % HID;
        es[n] = emb[(long long)sid[tt] * HID + k];
    }
    __syncthreads();

    float acc[TB];
#pragma unroll
    for (int tt = 0; tt < TB; tt++) acc[tt] = 0.f;

    const float* wr = W_ih + tid * HID;
#pragma unroll 4
    for (int k = 0; k < HID; k++) {
        float w = __ldg(&wr[k]);
#pragma unroll
        for (int tt = 0; tt < TB; tt++) acc[tt] += w * es[tt * HID + k];
    }
    float b = b_ih[tid] + b_hh[tid];
#pragma unroll
    for (int tt = 0; tt < TB; tt++)
        g_xp[(t0 + tt) * G4 + tid] = acc[tt] + b;
}

// ---------------------------------------------------------------------------
// Kernel 2: sequential LSTM recurrence — single persistent CTA.
// Thread i owns gate-row i of W_hh (100 floats = 50 f32x2 register pairs).
// h lives in SMEM; matvec uses packed fma.rn.f32x2; activations distributed.
// ---------------------------------------------------------------------------
__global__ void __launch_bounds__(G4, 1)
lstm_kernel(const float* __restrict__ W_hh,
            const float* __restrict__ fc_w, const float* __restrict__ fc_b,
            float* __restrict__ out) {
    __shared__ __align__(16) float h_sh[HID];
    __shared__ float act[G4];
    const int i = threadIdx.x;

    // preload W_hh row i into register pairs (LDS-free mainloop for weights)
    unsigned long long w2[50];
    {
        const float2* wr = (const float2*)(W_hh + i * HID);
#pragma unroll
        for (int j = 0; j < 50; j++) {
            float2 t = wr[j];
            asm("mov.b64 %0, {%1, %2};" : "=l"(w2[j]) : "f"(t.x), "f"(t.y));
        }
    }

    if (i < HID) h_sh[i] = 0.f;
    float c = 0.f;
    __syncthreads();

    const float* xp = g_xp;
    for (int t = 0; t < SEQ; t++) {
        // issue early: latency hidden under the matvec below (x_proj is L2-hot)
        float xv = __ldg(&xp[t * G4 + i]);

        unsigned long long acc0 = 0ull, acc1 = 0ull;  // bit pattern == (0.f,0.f)
        const ulonglong2* h2 = (const ulonglong2*)h_sh;
#pragma unroll
        for (int j = 0; j < 25; j++) {
            ulonglong2 hv = h2[j];          // LDS.128, broadcast (same addr all lanes)
            acc0 = ffma2(w2[2 * j],     hv.x, acc0);
            acc1 = ffma2(w2[2 * j + 1], hv.y, acc1);
        }
        float a0, a1, b0, b1;
        unpack2(acc0, a0, a1);
        unpack2(acc1, b0, b1);
        float g = xv + ((a0 + b0) + (a1 + b1));

        // PyTorch gate order: rows [0,100)=i sig, [100,200)=f sig,
        // [200,300)=g tanh, [300,400)=o sig
        float a = (i < 200 || i >= 300) ? sig_f(g) : tanh_f(g);
        act[i] = a;
        __syncthreads();

        if (i < HID) {
            float ig = act[i];
            float fg = act[i + HID];
            float gg = act[i + 2 * HID];
            float og = act[i + 3 * HID];
            c = fg * c + ig * gg;
            h_sh[i] = og * tanh_f(c);
        }
        __syncthreads();
    }

    // final FC: out[j] = h_last . fc_w[j] + fc_b[j]
    if (i < NCLS) {
        float s = fc_b[i];
        const float* fw = fc_w + i * HID;
#pragma unroll 4
        for (int k = 0; k < HID; k++) s += fw[k] * h_sh[k];
        out[i] = s;
    }
}

// ---------------------------------------------------------------------------
extern "C" void kernel_launch(void* const* d_in, const int* in_sizes, int n_in,
                              void* d_out, int out_size) {
    const int*   seq  = (const int*)d_in[0];
    const float* emb  = (const float*)d_in[1];
    const float* W_ih = (const float*)d_in[2];
    const float* W_hh = (const float*)d_in[3];
    const float* b_ih = (const float*)d_in[4];
    const float* b_hh = (const float*)d_in[5];
    const float* fc_w = (const float*)d_in[6];
    const float* fc_b = (const float*)d_in[7];
    float* out = (float*)d_out;

    proj_kernel<<<SEQ / TB, G4>>>(seq, emb, W_ih, b_ih, b_hh);
    lstm_kernel<<<1, G4>>>(W_hh, fc_w, fc_b, out);
}